// round 6
// baseline (speedup 1.0000x reference)
#include <cuda_runtime.h>
#include <math.h>
#include <stdint.h>

#define Bn 1024
#define En 512
#define Nn 1024
#define Mn 64
#define Pn 70
#define EPSf 1e-16f

#define TILE_ROWS 64
#define TILE_BYTES (TILE_ROWS * Mn * 4)   // 16384
#define NBUF 2
#define NTILES (Nn / TILE_ROWS)           // 16
#define NT 512                            // threads per CTA

// floats: tiles 8192 | wg 1024 | w 1024 | proj 80 | red 32 | sc 8 ; then 18 u64 mbars
#define SMEM_FLOATS (8192 + 1024 + 1024 + 80 + 32 + 8)
#define SMEM_BYTES  (SMEM_FLOATS * 4 + 18 * 8 + 16)

__device__ __forceinline__ float softplusf(float x) {
    return fmaxf(x, 0.0f) + log1pf(expf(-fabsf(x)));
}
__device__ __forceinline__ uint32_t s2u(const void* p) {
    return (uint32_t)__cvta_generic_to_shared(p);
}
__device__ __forceinline__ void mbar_init(uint32_t a, uint32_t cnt) {
    asm volatile("mbarrier.init.shared.b64 [%0], %1;" :: "r"(a), "r"(cnt) : "memory");
}
__device__ __forceinline__ void mbar_expect_tx(uint32_t a, uint32_t bytes) {
    asm volatile("mbarrier.arrive.expect_tx.shared.b64 _, [%0], %1;" :: "r"(a), "r"(bytes) : "memory");
}
__device__ __forceinline__ void mbar_arrive(uint32_t a) {
    asm volatile("mbarrier.arrive.shared.b64 _, [%0];" :: "r"(a) : "memory");
}
__device__ __forceinline__ void bulk_g2s(uint32_t dst, const void* src, uint32_t bytes, uint32_t mbar) {
    asm volatile("cp.async.bulk.shared::cta.global.mbarrier::complete_tx::bytes [%0], [%1], %2, [%3];"
                 :: "r"(dst), "l"(src), "r"(bytes), "r"(mbar) : "memory");
}
__device__ __forceinline__ void mbar_wait(uint32_t a, uint32_t parity) {
    asm volatile(
        "{\n\t.reg .pred P;\n\t"
        "W0_%=:\n\t"
        "mbarrier.try_wait.parity.acquire.cta.shared::cta.b64 P, [%0], %1, 0x989680;\n\t"
        "@P bra.uni W1_%=;\n\t"
        "bra.uni W0_%=;\n\t"
        "W1_%=:\n\t}"
        :: "r"(a), "r"(parity) : "memory");
}

// block-wide sum for 16 warps; broadcast via red[16+...]. Two syncthreads.
__device__ __forceinline__ float block_sum(float v, float* red, int lane, int wid) {
    #pragma unroll
    for (int o = 16; o; o >>= 1) v += __shfl_xor_sync(0xffffffffu, v, o);
    if (lane == 0) red[wid] = v;
    __syncthreads();
    if (wid == 0) {
        float x = (lane < 16) ? red[lane] : 0.0f;
        #pragma unroll
        for (int o = 8; o; o >>= 1) x += __shfl_xor_sync(0xffffffffu, x, o);
        if (lane == 0) red[16] = x;
    }
    __syncthreads();
    return red[16];
}

__global__ __launch_bounds__(NT, 4) void ntm_kernel(const float* __restrict__ emb,
                                                    const float* __restrict__ w_prev,
                                                    const float* __restrict__ memory,
                                                    const float* __restrict__ W,
                                                    const float* __restrict__ bias,
                                                    float* __restrict__ out_md,
                                                    float* __restrict__ out_w) {
    extern __shared__ float smem[];
    float*    tiles = smem;                     // 8192 floats (2 x 16KB); aliases part[16*64] in phase D
    float*    wg_sh = smem + 8192;              // 1024 ; alias es[512] in phase A
    float*    w_sh  = wg_sh + 1024;             // 1024 ; alias pp[280] in phase A
    float*    proj  = w_sh + 1024;              // 80 (16B aligned)
    float*    red   = proj + 80;                // 32
    float*    sc    = red + 32;                 // 8
    uint64_t* mbars = (uint64_t*)(sc + 8);      // full[0..15] per-tile, empty[16..17] per-buf
    float*    es    = wg_sh;
    float*    pp    = w_sh;

    const int b    = blockIdx.x;
    const int tid  = threadIdx.x;
    const int lane = tid & 31;
    const int wid  = tid >> 5;
    const float* mb = memory + (size_t)b * Nn * Mn;

    const uint32_t tiles_u = s2u(tiles);
    const uint32_t mbar0   = s2u(mbars);
    // full[t] = mbar0 + 8t (single-use, parity 0); empty[k] = mbar0 + 8*(16+k)

    if (tid == 0) {
        #pragma unroll
        for (int t = 0; t < NTILES; ++t) mbar_init(mbar0 + 8u * t, 1);
        #pragma unroll
        for (int k = 0; k < NBUF; ++k)   mbar_init(mbar0 + 8u * (NTILES + k), 32);
    }
    __syncthreads();

    // ---- producer start (thread 511: its own tile is the LAST one -> no self-deadlock) ----
    if (tid == NT - 1) {
        #pragma unroll
        for (int i = 0; i < NBUF; ++i) {
            uint32_t fb = mbar0 + 8u * i;
            mbar_expect_tx(fb, TILE_BYTES);
            bulk_g2s(tiles_u + i * TILE_BYTES, mb + (size_t)i * TILE_ROWS * Mn, TILE_BYTES, fb);
        }
    }

    // ---- Phase A: proj = emb[b] @ W + bias (split-K: 70 cols x 4 chunks of 128) ----
    if (tid < En) es[tid] = emb[(size_t)b * En + tid];
    __syncthreads();
    if (tid < Pn * 4) {
        int c = tid >> 2, chunk = tid & 3;
        int e0 = chunk * 128;
        float acc = 0.0f;
        #pragma unroll 8
        for (int e = e0; e < e0 + 128; ++e)
            acc = fmaf(es[e], W[e * Pn + c], acc);
        pp[tid] = acc;
    }
    __syncthreads();
    if (tid < Pn) {
        float a = bias[tid];
        #pragma unroll
        for (int j = 0; j < 4; ++j) a += pp[tid * 4 + j];
        proj[tid] = a;
    }
    __syncthreads();
    if (tid < 64) {
        float kv = proj[tid];
        float ksq = kv * kv;
        #pragma unroll
        for (int o = 16; o; o >>= 1) ksq += __shfl_xor_sync(0xffffffffu, ksq, o);
        if (lane == 0) red[wid] = ksq;
    }
    __syncthreads();
    if (tid == 0) {
        sc[6] = sqrtf(red[0] + red[1]);                 // k_norm
        float a0 = proj[Mn + 2], a1 = proj[Mn + 3], a2 = proj[Mn + 4];
        sc[0] = softplusf(proj[Mn + 0]);                // beta
        sc[1] = 1.0f / (1.0f + expf(-proj[Mn + 1]));    // g
        float mx = fmaxf(a0, fmaxf(a1, a2));
        float e0 = expf(a0 - mx), e1 = expf(a1 - mx), e2 = expf(a2 - mx);
        float dn = e0 + e1 + e2;
        sc[2] = e0 / dn; sc[3] = e1 / dn; sc[4] = e2 / dn;
        sc[5] = 1.0f + softplusf(proj[Mn + 5]);         // y
    }
    __syncthreads();

    const float beta  = sc[0];
    const float knorm = sc[6];
    const float2 wprev2 = ((const float2*)(w_prev + (size_t)b * Nn))[tid];  // n=2t,2t+1

    // ---- producer: remaining tiles; empty[buf] waited strictly in order ----
    if (tid == NT - 1) {
        for (int i = NBUF; i < NTILES; ++i) {
            int buf = i & 1;
            mbar_wait(mbar0 + 8u * (NTILES + buf), ((i >> 1) - 1) & 1);
            uint32_t fb = mbar0 + 8u * i;
            mbar_expect_tx(fb, TILE_BYTES);
            bulk_g2s(tiles_u + buf * TILE_BYTES, mb + (size_t)i * TILE_ROWS * Mn, TILE_BYTES, fb);
        }
    }

    // ---- Phase B: thread t -> rows 2t, 2t+1 of tile t>>5 (no shuffles, k amortized x2) ----
    float z0, z1;
    {
        const int tile = tid >> 5;
        const int buf  = tile & 1;
        mbar_wait(mbar0 + 8u * tile, 0);
        const float4* va = (const float4*)(tiles + buf * 4096 + ((tid & 31) * 2) * 64);
        const float4* vb = va + 16;
        const float4* k4 = (const float4*)proj;
        const int rot = tid & 15;
        float d0 = 0.f, q0 = 0.f, d1 = 0.f, q1 = 0.f;
        #pragma unroll 2
        for (int j = 0; j < 16; ++j) {
            int j0 = (j + rot) & 15;
            float4 kk = k4[j0];
            float4 v0 = va[j0];
            float4 v1 = vb[j0];
            d0 = fmaf(kk.x, v0.x, fmaf(kk.y, v0.y, fmaf(kk.z, v0.z, fmaf(kk.w, v0.w, d0))));
            q0 = fmaf(v0.x, v0.x, fmaf(v0.y, v0.y, fmaf(v0.z, v0.z, fmaf(v0.w, v0.w, q0))));
            d1 = fmaf(kk.x, v1.x, fmaf(kk.y, v1.y, fmaf(kk.z, v1.z, fmaf(kk.w, v1.w, d1))));
            q1 = fmaf(v1.x, v1.x, fmaf(v1.y, v1.y, fmaf(v1.z, v1.z, fmaf(v1.w, v1.w, q1))));
        }
        z0 = beta * d0 / (knorm * sqrtf(q0) + EPSf);
        z1 = beta * d1 / (knorm * sqrtf(q1) + EPSf);
        mbar_arrive(mbar0 + 8u * (NTILES + buf));
    }

    // ---- Phase C: softmax (no max pass: |z| <= beta), gate, shift, sharpen ----
    float e0 = expf(z0), e1 = expf(z1);
    float denom = block_sum(e0 + e1, red, lane, wid);
    float inv_d = 1.0f / denom;
    float gg  = sc[1];
    float omg = 1.0f - gg;
    float wg0 = fmaf(gg, e0 * inv_d, omg * wprev2.x);
    float wg1 = fmaf(gg, e1 * inv_d, omg * wprev2.y);
    wg_sh[2 * tid]     = wg0;
    wg_sh[2 * tid + 1] = wg1;
    __syncthreads();
    float s0 = sc[2], s1 = sc[3], s2 = sc[4], yy = sc[5];
    float wt0 = s0 * wg1 + s1 * wg0 + s2 * wg_sh[(2 * tid - 1) & (Nn - 1)];
    float wt1 = s0 * wg_sh[(2 * tid + 2) & (Nn - 1)] + s1 * wg1 + s2 * wg0;
    float wp0 = __powf(wt0, yy);
    float wp1 = __powf(wt1, yy);
    float psum = block_sum(wp0 + wp1, red, lane, wid);
    float inv_p = 1.0f / (psum + EPSf);
    float wv0 = wp0 * inv_p, wv1 = wp1 * inv_p;
    w_sh[2 * tid]     = wv0;
    w_sh[2 * tid + 1] = wv1;
    ((float2*)(out_w + (size_t)b * Nn))[tid] = make_float2(wv0, wv1);
    __syncthreads();   // w_sh ready; tiles drained -> reuse as partials

    // ---- Phase D: pass 2 (L2-hot, reverse order = most-recent-first) ----
    const int sub  = lane & 15;
    const int half = lane >> 4;
    float4 acc = make_float4(0.f, 0.f, 0.f, 0.f);
    #pragma unroll 4
    for (int it = 31; it >= 0; --it) {
        int n = it * 32 + wid * 2 + half;
        float4 v = ((const float4*)(mb + (size_t)n * Mn))[sub];
        float wn = w_sh[n];
        acc.x = fmaf(wn, v.x, acc.x);
        acc.y = fmaf(wn, v.y, acc.y);
        acc.z = fmaf(wn, v.z, acc.z);
        acc.w = fmaf(wn, v.w, acc.w);
    }
    acc.x += __shfl_xor_sync(0xffffffffu, acc.x, 16);
    acc.y += __shfl_xor_sync(0xffffffffu, acc.y, 16);
    acc.z += __shfl_xor_sync(0xffffffffu, acc.z, 16);
    acc.w += __shfl_xor_sync(0xffffffffu, acc.w, 16);
    if (half == 0)
        ((float4*)tiles)[wid * 16 + sub] = acc;       // part[wid][64]
    __syncthreads();
    if (tid < Mn) {
        float s = 0.0f;
        #pragma unroll
        for (int w = 0; w < 16; ++w) s += tiles[w * 64 + tid];
        out_md[(size_t)b * Mn + tid] = s;
    }
}

extern "C" void kernel_launch(void* const* d_in, const int* in_sizes, int n_in,
                              void* d_out, int out_size) {
    const float* embeddings = (const float*)d_in[0];   // [1024, 512]
    const float* w_prev     = (const float*)d_in[1];   // [1024, 1024]
    const float* memory     = (const float*)d_in[2];   // [1024, 1024, 64]
    const float* W          = (const float*)d_in[3];   // [512, 70]
    const float* bias       = (const float*)d_in[4];   // [70]

    float* out_md = (float*)d_out;             // memory_data [1024, 64] first
    float* out_w  = out_md + (size_t)Bn * Mn;  // then w [1024, 1024]

    cudaFuncSetAttribute(ntm_kernel, cudaFuncAttributeMaxDynamicSharedMemorySize, SMEM_BYTES);
    ntm_kernel<<<Bn, NT, SMEM_BYTES>>>(embeddings, w_prev, memory, W, bias, out_md, out_w);
}

// round 7
// speedup vs baseline: 1.0091x; 1.0091x over previous
#include <cuda_runtime.h>
#include <math.h>
#include <stdint.h>

#define Bn 1024
#define En 512
#define Nn 1024
#define Mn 64
#define Pn 70
#define EPSf 1e-16f

// scratch: z[B,N] and per-b params (k[64], beta, g, s0,s1,s2, y, knorm)
__device__ float g_z[Bn * Nn];
__device__ float g_p[Bn * 80];

__device__ __forceinline__ float softplusf(float x) {
    return fmaxf(x, 0.0f) + log1pf(expf(-fabsf(x)));
}
__device__ __forceinline__ uint32_t s2u(const void* p) {
    return (uint32_t)__cvta_generic_to_shared(p);
}
__device__ __forceinline__ void mbar_init(uint32_t a, uint32_t cnt) {
    asm volatile("mbarrier.init.shared.b64 [%0], %1;" :: "r"(a), "r"(cnt) : "memory");
}
__device__ __forceinline__ void mbar_expect_tx(uint32_t a, uint32_t bytes) {
    asm volatile("mbarrier.arrive.expect_tx.shared.b64 _, [%0], %1;" :: "r"(a), "r"(bytes) : "memory");
}
__device__ __forceinline__ void mbar_arrive(uint32_t a) {
    asm volatile("mbarrier.arrive.shared.b64 _, [%0];" :: "r"(a) : "memory");
}
__device__ __forceinline__ void bulk_g2s(uint32_t dst, const void* src, uint32_t bytes, uint32_t mbar) {
    asm volatile("cp.async.bulk.shared::cta.global.mbarrier::complete_tx::bytes [%0], [%1], %2, [%3];"
                 :: "r"(dst), "l"(src), "r"(bytes), "r"(mbar) : "memory");
}
__device__ __forceinline__ void mbar_wait(uint32_t a, uint32_t parity) {
    asm volatile(
        "{\n\t.reg .pred P;\n\t"
        "W0_%=:\n\t"
        "mbarrier.try_wait.parity.acquire.cta.shared::cta.b64 P, [%0], %1, 0x989680;\n\t"
        "@P bra.uni W1_%=;\n\t"
        "bra.uni W0_%=;\n\t"
        "W1_%=:\n\t}"
        :: "r"(a), "r"(parity) : "memory");
}

// ===================== K1: proj + derived scalars =====================
__global__ __launch_bounds__(320) void proj_kernel(const float* __restrict__ emb,
                                                   const float* __restrict__ W,
                                                   const float* __restrict__ bias) {
    __shared__ float es[En];
    __shared__ float pp[Pn * 4];
    __shared__ float pr[Pn + 2];
    __shared__ float red[2];
    const int b = blockIdx.x, tid = threadIdx.x;
    for (int i = tid; i < En; i += 320) es[i] = emb[(size_t)b * En + i];
    __syncthreads();
    if (tid < Pn * 4) {
        int c = tid >> 2, ch = tid & 3, e0 = ch * 128;
        float acc = 0.0f;
        #pragma unroll 8
        for (int e = e0; e < e0 + 128; ++e)
            acc = fmaf(es[e], W[e * Pn + c], acc);
        pp[tid] = acc;
    }
    __syncthreads();
    if (tid < Pn)
        pr[tid] = bias[tid] + pp[4 * tid] + pp[4 * tid + 1] + pp[4 * tid + 2] + pp[4 * tid + 3];
    __syncthreads();
    if (tid < 64) {
        float kv = pr[tid];
        g_p[b * 80 + tid] = kv;
        float ksq = kv * kv;
        #pragma unroll
        for (int o = 16; o; o >>= 1) ksq += __shfl_xor_sync(0xffffffffu, ksq, o);
        if ((tid & 31) == 0) red[tid >> 5] = ksq;
    }
    __syncthreads();
    if (tid == 0) {
        float a0 = pr[Mn + 2], a1 = pr[Mn + 3], a2 = pr[Mn + 4];
        float mx = fmaxf(a0, fmaxf(a1, a2));
        float e0 = expf(a0 - mx), e1 = expf(a1 - mx), e2 = expf(a2 - mx);
        float dn = e0 + e1 + e2;
        g_p[b * 80 + 64] = softplusf(pr[Mn + 0]);               // beta
        g_p[b * 80 + 65] = 1.0f / (1.0f + expf(-pr[Mn + 1]));   // g
        g_p[b * 80 + 66] = e0 / dn;
        g_p[b * 80 + 67] = e1 / dn;
        g_p[b * 80 + 68] = e2 / dn;
        g_p[b * 80 + 69] = 1.0f + softplusf(pr[Mn + 5]);        // y
        g_p[b * 80 + 70] = sqrtf(red[0] + red[1]);              // k_norm
    }
}

// ===================== K2: z = beta * cos-sim — pure stream =====================
// CTA = (b, half of 512 rows). 8 tiles x 16KB through 4 buffers, warp w -> tile w.
#define K2_TB 16384
#define K2_SMEM_BYTES (4 * K2_TB + 64 * 4 + 12 * 8)

__global__ __launch_bounds__(256) void sim_kernel(const float* __restrict__ memory) {
    extern __shared__ float smem[];
    float*    tiles = smem;                       // 16384 floats (4 x 16KB)
    float*    k_sh  = smem + 16384;               // 64
    uint64_t* mbars = (uint64_t*)(k_sh + 64);     // full[0..7] per-tile, empty[8..11] per-buf

    const int b    = blockIdx.x >> 1;
    const int half = blockIdx.x & 1;
    const int tid  = threadIdx.x;
    const int lane = tid & 31;
    const int wid  = tid >> 5;                    // 0..7, warp w consumes tile w
    const float* mb = memory + ((size_t)b * Nn + half * 512) * Mn;

    const uint32_t tiles_u = s2u(tiles);
    const uint32_t mbar0   = s2u(mbars);
    // full[t] = mbar0+8t (single-use, parity 0); empty[k] = mbar0+8*(8+k)

    if (tid == 0) {
        #pragma unroll
        for (int t = 0; t < 8; ++t) mbar_init(mbar0 + 8u * t, 1);
        #pragma unroll
        for (int k = 0; k < 4; ++k) mbar_init(mbar0 + 8u * (8 + k), 32);
    }
    if (tid < 64) k_sh[tid] = g_p[b * 80 + tid];
    const float beta  = g_p[b * 80 + 64];
    const float knorm = g_p[b * 80 + 70];
    __syncthreads();

    // producer: thread 255 (warp 7 -> its own tile is last; no self-deadlock)
    if (tid == 255) {
        #pragma unroll
        for (int i = 0; i < 8; ++i) {
            int buf = i & 3;
            if (i >= 4) mbar_wait(mbar0 + 8u * (8 + buf), 0);
            uint32_t fb = mbar0 + 8u * i;
            mbar_expect_tx(fb, K2_TB);
            bulk_g2s(tiles_u + buf * K2_TB, mb + (size_t)i * 64 * Mn, K2_TB, fb);
        }
    }

    // consumer: warp wid waits its tile, thread handles rows 2*lane, 2*lane+1
    mbar_wait(mbar0 + 8u * wid, 0);
    const float4* base = (const float4*)(tiles + (wid & 3) * 4096);
    const float4* va = base + lane * 32;
    const float4* vb = va + 16;
    const float4* k4 = (const float4*)k_sh;
    const int rot = lane & 15;
    float d0 = 0.f, q0 = 0.f, d1 = 0.f, q1 = 0.f;
    #pragma unroll 2
    for (int j = 0; j < 16; ++j) {
        int j0 = (j + rot) & 15;
        float4 kk = k4[j0];
        float4 v0 = va[j0];
        float4 v1 = vb[j0];
        d0 = fmaf(kk.x, v0.x, fmaf(kk.y, v0.y, fmaf(kk.z, v0.z, fmaf(kk.w, v0.w, d0))));
        q0 = fmaf(v0.x, v0.x, fmaf(v0.y, v0.y, fmaf(v0.z, v0.z, fmaf(v0.w, v0.w, q0))));
        d1 = fmaf(kk.x, v1.x, fmaf(kk.y, v1.y, fmaf(kk.z, v1.z, fmaf(kk.w, v1.w, d1))));
        q1 = fmaf(v1.x, v1.x, fmaf(v1.y, v1.y, fmaf(v1.z, v1.z, fmaf(v1.w, v1.w, q1))));
    }
    float z0 = beta * d0 / (knorm * sqrtf(q0) + EPSf);
    float z1 = beta * d1 / (knorm * sqrtf(q1) + EPSf);
    mbar_arrive(mbar0 + 8u * (8 + (wid & 3)));
    ((float2*)(g_z + (size_t)b * Nn + half * 512 + wid * 64))[lane] = make_float2(z0, z1);
}

// ===================== K34: softmax chain + weighted read =====================
__device__ __forceinline__ float block_sum512(float v, float* red, int lane, int wid) {
    #pragma unroll
    for (int o = 16; o; o >>= 1) v += __shfl_xor_sync(0xffffffffu, v, o);
    if (lane == 0) red[wid] = v;
    __syncthreads();
    if (wid == 0) {
        float x = (lane < 16) ? red[lane] : 0.0f;
        #pragma unroll
        for (int o = 8; o; o >>= 1) x += __shfl_xor_sync(0xffffffffu, x, o);
        if (lane == 0) red[16] = x;
    }
    __syncthreads();
    return red[16];
}

__global__ __launch_bounds__(512) void read_kernel(const float* __restrict__ w_prev,
                                                   const float* __restrict__ memory,
                                                   float* __restrict__ out_md,
                                                   float* __restrict__ out_w) {
    __shared__ float wg_sh[Nn];     // also reused as partials [16][64] in phase D
    __shared__ float w_sh[Nn];
    __shared__ float red[17];
    const int b    = blockIdx.x;
    const int tid  = threadIdx.x;
    const int lane = tid & 31;
    const int wid  = tid >> 5;      // 0..15
    const float* mb = memory + (size_t)b * Nn * Mn;

    float2 z2 = ((const float2*)(g_z + (size_t)b * Nn))[tid];
    float2 wprev2 = ((const float2*)(w_prev + (size_t)b * Nn))[tid];
    const float gg = g_p[b * 80 + 65];
    const float s0 = g_p[b * 80 + 66];
    const float s1 = g_p[b * 80 + 67];
    const float s2 = g_p[b * 80 + 68];
    const float yy = g_p[b * 80 + 69];

    float e0 = expf(z2.x), e1 = expf(z2.y);     // |z| <= beta, no max pass needed
    float denom = block_sum512(e0 + e1, red, lane, wid);
    float inv_d = 1.0f / denom;
    float omg = 1.0f - gg;
    float wg0 = fmaf(gg, e0 * inv_d, omg * wprev2.x);
    float wg1 = fmaf(gg, e1 * inv_d, omg * wprev2.y);
    wg_sh[2 * tid]     = wg0;
    wg_sh[2 * tid + 1] = wg1;
    __syncthreads();
    float wt0 = s0 * wg1 + s1 * wg0 + s2 * wg_sh[(2 * tid - 1) & (Nn - 1)];
    float wt1 = s0 * wg_sh[(2 * tid + 2) & (Nn - 1)] + s1 * wg1 + s2 * wg0;
    float wp0 = __powf(wt0, yy);
    float wp1 = __powf(wt1, yy);
    float psum = block_sum512(wp0 + wp1, red, lane, wid);
    float inv_p = 1.0f / (psum + EPSf);
    float wv0 = wp0 * inv_p, wv1 = wp1 * inv_p;
    w_sh[2 * tid]     = wv0;
    w_sh[2 * tid + 1] = wv1;
    ((float2*)(out_w + (size_t)b * Nn))[tid] = make_float2(wv0, wv1);
    __syncthreads();   // w_sh ready; wg_sh reads done -> reuse as partials

    // weighted sum: warp covers 2 contiguous rows per iter (512B contiguous)
    const int sub  = lane & 15;
    const int half = lane >> 4;
    float4 acc = make_float4(0.f, 0.f, 0.f, 0.f);
    #pragma unroll 4
    for (int it = 0; it < 32; ++it) {
        int n = it * 32 + wid * 2 + half;
        float4 v = ((const float4*)(mb + (size_t)n * Mn))[sub];
        float wn = w_sh[n];
        acc.x = fmaf(wn, v.x, acc.x);
        acc.y = fmaf(wn, v.y, acc.y);
        acc.z = fmaf(wn, v.z, acc.z);
        acc.w = fmaf(wn, v.w, acc.w);
    }
    acc.x += __shfl_xor_sync(0xffffffffu, acc.x, 16);
    acc.y += __shfl_xor_sync(0xffffffffu, acc.y, 16);
    acc.z += __shfl_xor_sync(0xffffffffu, acc.z, 16);
    acc.w += __shfl_xor_sync(0xffffffffu, acc.w, 16);
    if (half == 0)
        ((float4*)wg_sh)[wid * 16 + sub] = acc;     // partials [16][64]
    __syncthreads();
    if (tid < Mn) {
        float s = 0.0f;
        #pragma unroll
        for (int w = 0; w < 16; ++w) s += wg_sh[w * 64 + tid];
        out_md[(size_t)b * Mn + tid] = s;
    }
}

extern "C" void kernel_launch(void* const* d_in, const int* in_sizes, int n_in,
                              void* d_out, int out_size) {
    const float* embeddings = (const float*)d_in[0];   // [1024, 512]
    const float* w_prev     = (const float*)d_in[1];   // [1024, 1024]
    const float* memory     = (const float*)d_in[2];   // [1024, 1024, 64]
    const float* W          = (const float*)d_in[3];   // [512, 70]
    const float* bias       = (const float*)d_in[4];   // [70]

    float* out_md = (float*)d_out;             // memory_data [1024, 64] first
    float* out_w  = out_md + (size_t)Bn * Mn;  // then w [1024, 1024]

    proj_kernel<<<Bn, 320>>>(embeddings, W, bias);
    cudaFuncSetAttribute(sim_kernel, cudaFuncAttributeMaxDynamicSharedMemorySize, K2_SMEM_BYTES);
    sim_kernel<<<2 * Bn, 256, K2_SMEM_BYTES>>>(memory);
    read_kernel<<<Bn, 512>>>(w_prev, memory, out_md, out_w);
}

// round 8
// speedup vs baseline: 1.3715x; 1.3592x over previous
#include <cuda_runtime.h>
#include <math.h>
#include <stdint.h>

#define Bn 1024
#define En 512
#define Nn 1024
#define Mn 64
#define Pn 70
#define EPSf 1e-16f

// scratch: z[B,N] and per-b params (k[64], beta, g, s0,s1,s2, y, knorm)
__device__ float g_z[Bn * Nn];
__device__ float g_p[Bn * 80];

__device__ __forceinline__ float softplusf(float x) {
    return fmaxf(x, 0.0f) + log1pf(expf(-fabsf(x)));
}
__device__ __forceinline__ uint32_t s2u(const void* p) {
    return (uint32_t)__cvta_generic_to_shared(p);
}
__device__ __forceinline__ void mbar_init(uint32_t a, uint32_t cnt) {
    asm volatile("mbarrier.init.shared.b64 [%0], %1;" :: "r"(a), "r"(cnt) : "memory");
}
__device__ __forceinline__ void mbar_expect_tx(uint32_t a, uint32_t bytes) {
    asm volatile("mbarrier.arrive.expect_tx.shared.b64 _, [%0], %1;" :: "r"(a), "r"(bytes) : "memory");
}
__device__ __forceinline__ void mbar_arrive(uint32_t a) {
    asm volatile("mbarrier.arrive.shared.b64 _, [%0];" :: "r"(a) : "memory");
}
__device__ __forceinline__ void bulk_g2s(uint32_t dst, const void* src, uint32_t bytes, uint32_t mbar) {
    asm volatile("cp.async.bulk.shared::cta.global.mbarrier::complete_tx::bytes [%0], [%1], %2, [%3];"
                 :: "r"(dst), "l"(src), "r"(bytes), "r"(mbar) : "memory");
}
__device__ __forceinline__ void mbar_wait(uint32_t a, uint32_t parity) {
    asm volatile(
        "{\n\t.reg .pred P;\n\t"
        "W0_%=:\n\t"
        "mbarrier.try_wait.parity.acquire.cta.shared::cta.b64 P, [%0], %1, 0x989680;\n\t"
        "@P bra.uni W1_%=;\n\t"
        "bra.uni W0_%=;\n\t"
        "W1_%=:\n\t}"
        :: "r"(a), "r"(parity) : "memory");
}

// ===================== K1: proj GEMM with W fully smem-resident =====================
// grid 128, block 576; CTA owns 8 batch rows. smem: W[512*70] + emb[8*512] + pr[560]
#define K1_WF   (En * Pn)          // 35840 floats
#define K1_EF   (8 * En)           // 4096 floats
#define K1_SMEM ((K1_WF + K1_EF + 560 + 16) * 4)

__global__ __launch_bounds__(576) void proj_kernel(const float* __restrict__ emb,
                                                   const float* __restrict__ W,
                                                   const float* __restrict__ bias) {
    extern __shared__ float s1[];
    float* W_sh = s1;                       // 35840
    float* e_sh = s1 + K1_WF;               // 4096
    float* pr   = s1 + K1_WF + K1_EF;       // 560

    const int tid  = threadIdx.x;
    const int lane = tid & 31;
    const int wid  = tid >> 5;
    const int b0   = blockIdx.x * 8;

    // coalesced float4 loads of W and 8 emb rows
    {
        const float4* Wv = (const float4*)W;
        float4* Ws = (float4*)W_sh;
        for (int i = tid; i < K1_WF / 4; i += 576) Ws[i] = Wv[i];
        const float4* Ev = (const float4*)(emb + (size_t)b0 * En);
        float4* Es = (float4*)e_sh;
        for (int i = tid; i < K1_EF / 4; i += 576) Es[i] = Ev[i];
    }
    __syncthreads();

    if (tid < 560) {
        const int r = tid / 70, c = tid - r * 70;
        const float* er = e_sh + r * En;
        float a0 = 0.f, a1 = 0.f, a2 = 0.f, a3 = 0.f;
        #pragma unroll 8
        for (int e = 0; e < En; e += 4) {
            float4 ev = *(const float4*)(er + e);
            a0 = fmaf(ev.x, W_sh[(e + 0) * Pn + c], a0);
            a1 = fmaf(ev.y, W_sh[(e + 1) * Pn + c], a1);
            a2 = fmaf(ev.z, W_sh[(e + 2) * Pn + c], a2);
            a3 = fmaf(ev.w, W_sh[(e + 3) * Pn + c], a3);
        }
        pr[tid] = bias[c] + ((a0 + a1) + (a2 + a3));
    }
    __syncthreads();

    // per-row scalars: warp `wid` handles row `wid` (wid < 8)
    if (wid < 8) {
        const int bb = b0 + wid;
        const float* prr = pr + wid * 70;
        float kv0 = prr[2 * lane], kv1 = prr[2 * lane + 1];
        g_p[bb * 80 + 2 * lane]     = kv0;
        g_p[bb * 80 + 2 * lane + 1] = kv1;
        float ksq = kv0 * kv0 + kv1 * kv1;
        #pragma unroll
        for (int o = 16; o; o >>= 1) ksq += __shfl_xor_sync(0xffffffffu, ksq, o);
        if (lane == 0) {
            float a0 = prr[Mn + 2], a1 = prr[Mn + 3], a2 = prr[Mn + 4];
            float mx = fmaxf(a0, fmaxf(a1, a2));
            float e0 = expf(a0 - mx), e1 = expf(a1 - mx), e2 = expf(a2 - mx);
            float dn = e0 + e1 + e2;
            g_p[bb * 80 + 64] = softplusf(prr[Mn + 0]);               // beta
            g_p[bb * 80 + 65] = 1.0f / (1.0f + expf(-prr[Mn + 1]));   // g
            g_p[bb * 80 + 66] = e0 / dn;
            g_p[bb * 80 + 67] = e1 / dn;
            g_p[bb * 80 + 68] = e2 / dn;
            g_p[bb * 80 + 69] = 1.0f + softplusf(prr[Mn + 5]);        // y
            g_p[bb * 80 + 70] = sqrtf(ksq);                           // k_norm
        }
    }
}

// ===================== K2: z = beta * cos-sim — pure stream =====================
// CTA = (b, half of 512 rows). 8 tiles x 16KB through 4 buffers, warp w -> tile w.
#define K2_TB 16384
#define K2_SMEM_BYTES (4 * K2_TB + 64 * 4 + 12 * 8)

__global__ __launch_bounds__(256) void sim_kernel(const float* __restrict__ memory) {
    extern __shared__ float smem[];
    float*    tiles = smem;                       // 16384 floats (4 x 16KB)
    float*    k_sh  = smem + 16384;               // 64
    uint64_t* mbars = (uint64_t*)(k_sh + 64);     // full[0..7] per-tile, empty[8..11] per-buf

    const int b    = blockIdx.x >> 1;
    const int half = blockIdx.x & 1;
    const int tid  = threadIdx.x;
    const int lane = tid & 31;
    const int wid  = tid >> 5;                    // 0..7, warp w consumes tile w
    const float* mb = memory + ((size_t)b * Nn + half * 512) * Mn;

    const uint32_t tiles_u = s2u(tiles);
    const uint32_t mbar0   = s2u(mbars);
    // full[t] = mbar0+8t (single-use, parity 0); empty[k] = mbar0+8*(8+k)

    if (tid == 0) {
        #pragma unroll
        for (int t = 0; t < 8; ++t) mbar_init(mbar0 + 8u * t, 1);
        #pragma unroll
        for (int k = 0; k < 4; ++k) mbar_init(mbar0 + 8u * (8 + k), 32);
    }
    if (tid < 64) k_sh[tid] = g_p[b * 80 + tid];
    const float beta  = g_p[b * 80 + 64];
    const float knorm = g_p[b * 80 + 70];
    __syncthreads();

    // producer: thread 255 (warp 7 -> its own tile is last; no self-deadlock)
    if (tid == 255) {
        #pragma unroll
        for (int i = 0; i < 8; ++i) {
            int buf = i & 3;
            if (i >= 4) mbar_wait(mbar0 + 8u * (8 + buf), 0);
            uint32_t fb = mbar0 + 8u * i;
            mbar_expect_tx(fb, K2_TB);
            bulk_g2s(tiles_u + buf * K2_TB, mb + (size_t)i * 64 * Mn, K2_TB, fb);
        }
    }

    // consumer: warp wid waits its tile, thread handles rows 2*lane, 2*lane+1
    mbar_wait(mbar0 + 8u * wid, 0);
    const float4* base = (const float4*)(tiles + (wid & 3) * 4096);
    const float4* va = base + lane * 32;
    const float4* vb = va + 16;
    const float4* k4 = (const float4*)k_sh;
    const int rot = lane & 15;
    float d0 = 0.f, q0 = 0.f, d1 = 0.f, q1 = 0.f;
    #pragma unroll 2
    for (int j = 0; j < 16; ++j) {
        int j0 = (j + rot) & 15;
        float4 kk = k4[j0];
        float4 v0 = va[j0];
        float4 v1 = vb[j0];
        d0 = fmaf(kk.x, v0.x, fmaf(kk.y, v0.y, fmaf(kk.z, v0.z, fmaf(kk.w, v0.w, d0))));
        q0 = fmaf(v0.x, v0.x, fmaf(v0.y, v0.y, fmaf(v0.z, v0.z, fmaf(v0.w, v0.w, q0))));
        d1 = fmaf(kk.x, v1.x, fmaf(kk.y, v1.y, fmaf(kk.z, v1.z, fmaf(kk.w, v1.w, d1))));
        q1 = fmaf(v1.x, v1.x, fmaf(v1.y, v1.y, fmaf(v1.z, v1.z, fmaf(v1.w, v1.w, q1))));
    }
    float z0 = beta * d0 / (knorm * sqrtf(q0) + EPSf);
    float z1 = beta * d1 / (knorm * sqrtf(q1) + EPSf);
    mbar_arrive(mbar0 + 8u * (8 + (wid & 3)));
    ((float2*)(g_z + (size_t)b * Nn + half * 512 + wid * 64))[lane] = make_float2(z0, z1);
}

// ===================== K34: softmax chain + weighted read =====================
__device__ __forceinline__ float block_sum512(float v, float* red, int lane, int wid) {
    #pragma unroll
    for (int o = 16; o; o >>= 1) v += __shfl_xor_sync(0xffffffffu, v, o);
    if (lane == 0) red[wid] = v;
    __syncthreads();
    if (wid == 0) {
        float x = (lane < 16) ? red[lane] : 0.0f;
        #pragma unroll
        for (int o = 8; o; o >>= 1) x += __shfl_xor_sync(0xffffffffu, x, o);
        if (lane == 0) red[16] = x;
    }
    __syncthreads();
    return red[16];
}

__global__ __launch_bounds__(512) void read_kernel(const float* __restrict__ w_prev,
                                                   const float* __restrict__ memory,
                                                   float* __restrict__ out_md,
                                                   float* __restrict__ out_w) {
    __shared__ float wg_sh[Nn];     // also reused as partials [16][64] in phase D
    __shared__ float w_sh[Nn];
    __shared__ float red[17];
    const int b    = blockIdx.x;
    const int tid  = threadIdx.x;
    const int lane = tid & 31;
    const int wid  = tid >> 5;      // 0..15
    const float* mb = memory + (size_t)b * Nn * Mn;

    float2 z2 = ((const float2*)(g_z + (size_t)b * Nn))[tid];
    float2 wprev2 = ((const float2*)(w_prev + (size_t)b * Nn))[tid];
    const float gg = g_p[b * 80 + 65];
    const float s0 = g_p[b * 80 + 66];
    const float s1 = g_p[b * 80 + 67];
    const float s2 = g_p[b * 80 + 68];
    const float yy = g_p[b * 80 + 69];

    float e0 = expf(z2.x), e1 = expf(z2.y);     // |z| <= beta, no max pass needed
    float denom = block_sum512(e0 + e1, red, lane, wid);
    float inv_d = 1.0f / denom;
    float omg = 1.0f - gg;
    float wg0 = fmaf(gg, e0 * inv_d, omg * wprev2.x);
    float wg1 = fmaf(gg, e1 * inv_d, omg * wprev2.y);
    wg_sh[2 * tid]     = wg0;
    wg_sh[2 * tid + 1] = wg1;
    __syncthreads();
    float wt0 = s0 * wg1 + s1 * wg0 + s2 * wg_sh[(2 * tid - 1) & (Nn - 1)];
    float wt1 = s0 * wg_sh[(2 * tid + 2) & (Nn - 1)] + s1 * wg1 + s2 * wg0;
    float wp0 = __powf(wt0, yy);
    float wp1 = __powf(wt1, yy);
    float psum = block_sum512(wp0 + wp1, red, lane, wid);
    float inv_p = 1.0f / (psum + EPSf);
    float wv0 = wp0 * inv_p, wv1 = wp1 * inv_p;
    w_sh[2 * tid]     = wv0;
    w_sh[2 * tid + 1] = wv1;
    ((float2*)(out_w + (size_t)b * Nn))[tid] = make_float2(wv0, wv1);
    __syncthreads();   // w_sh ready; wg_sh reads done -> reuse as partials

    // weighted sum: warp covers 2 contiguous rows per iter (512B contiguous)
    const int sub  = lane & 15;
    const int half = lane >> 4;
    float4 acc = make_float4(0.f, 0.f, 0.f, 0.f);
    #pragma unroll 4
    for (int it = 0; it < 32; ++it) {
        int n = it * 32 + wid * 2 + half;
        float4 v = ((const float4*)(mb + (size_t)n * Mn))[sub];
        float wn = w_sh[n];
        acc.x = fmaf(wn, v.x, acc.x);
        acc.y = fmaf(wn, v.y, acc.y);
        acc.z = fmaf(wn, v.z, acc.z);
        acc.w = fmaf(wn, v.w, acc.w);
    }
    acc.x += __shfl_xor_sync(0xffffffffu, acc.x, 16);
    acc.y += __shfl_xor_sync(0xffffffffu, acc.y, 16);
    acc.z += __shfl_xor_sync(0xffffffffu, acc.z, 16);
    acc.w += __shfl_xor_sync(0xffffffffu, acc.w, 16);
    if (half == 0)
        ((float4*)wg_sh)[wid * 16 + sub] = acc;     // partials [16][64]
    __syncthreads();
    if (tid < Mn) {
        float s = 0.0f;
        #pragma unroll
        for (int w = 0; w < 16; ++w) s += wg_sh[w * 64 + tid];
        out_md[(size_t)b * Mn + tid] = s;
    }
}

extern "C" void kernel_launch(void* const* d_in, const int* in_sizes, int n_in,
                              void* d_out, int out_size) {
    const float* embeddings = (const float*)d_in[0];   // [1024, 512]
    const float* w_prev     = (const float*)d_in[1];   // [1024, 1024]
    const float* memory     = (const float*)d_in[2];   // [1024, 1024, 64]
    const float* W          = (const float*)d_in[3];   // [512, 70]
    const float* bias       = (const float*)d_in[4];   // [70]

    float* out_md = (float*)d_out;             // memory_data [1024, 64] first
    float* out_w  = out_md + (size_t)Bn * Mn;  // then w [1024, 1024]

    cudaFuncSetAttribute(proj_kernel, cudaFuncAttributeMaxDynamicSharedMemorySize, K1_SMEM);
    proj_kernel<<<128, 576, K1_SMEM>>>(embeddings, W, bias);
    cudaFuncSetAttribute(sim_kernel, cudaFuncAttributeMaxDynamicSharedMemorySize, K2_SMEM_BYTES);
    sim_kernel<<<2 * Bn, 256, K2_SMEM_BYTES>>>(memory);
    read_kernel<<<Bn, 512>>>(w_prev, memory, out_md, out_w);
}

// round 9
// speedup vs baseline: 1.5492x; 1.1296x over previous
#include <cuda_runtime.h>
#include <math.h>
#include <stdint.h>

#define Bn 1024
#define En 512
#define Nn 1024
#define Mn 64
#define Pn 70
#define EPSf 1e-16f

// scratch: z[B,N]; proj partials g_pp[b][chunk][72]
__device__ float g_z[Bn * Nn];
__device__ float g_pp[Bn * 4 * 72];

__device__ __forceinline__ float softplusf(float x) {
    return fmaxf(x, 0.0f) + log1pf(expf(-fabsf(x)));
}
__device__ __forceinline__ uint32_t s2u(const void* p) {
    return (uint32_t)__cvta_generic_to_shared(p);
}
__device__ __forceinline__ void mbar_init(uint32_t a, uint32_t cnt) {
    asm volatile("mbarrier.init.shared.b64 [%0], %1;" :: "r"(a), "r"(cnt) : "memory");
}
__device__ __forceinline__ void mbar_expect_tx(uint32_t a, uint32_t bytes) {
    asm volatile("mbarrier.arrive.expect_tx.shared.b64 _, [%0], %1;" :: "r"(a), "r"(bytes) : "memory");
}
__device__ __forceinline__ void mbar_arrive(uint32_t a) {
    asm volatile("mbarrier.arrive.shared.b64 _, [%0];" :: "r"(a) : "memory");
}
__device__ __forceinline__ void bulk_g2s(uint32_t dst, const void* src, uint32_t bytes, uint32_t mbar) {
    asm volatile("cp.async.bulk.shared::cta.global.mbarrier::complete_tx::bytes [%0], [%1], %2, [%3];"
                 :: "r"(dst), "l"(src), "r"(bytes), "r"(mbar) : "memory");
}
__device__ __forceinline__ void mbar_wait(uint32_t a, uint32_t parity) {
    asm volatile(
        "{\n\t.reg .pred P;\n\t"
        "W0_%=:\n\t"
        "mbarrier.try_wait.parity.acquire.cta.shared::cta.b64 P, [%0], %1, 0x989680;\n\t"
        "@P bra.uni W1_%=;\n\t"
        "bra.uni W0_%=;\n\t"
        "W1_%=:\n\t}"
        :: "r"(a), "r"(parity) : "memory");
}

// ===================== K1: proj partials, 4-way split-K =====================
// 512 CTAs: group g = bx>>2 owns batch rows 8g..8g+7; chunk = bx&3 owns E range [128*chunk, +128)
__global__ __launch_bounds__(576) void proj_kernel(const float* __restrict__ emb,
                                                   const float* __restrict__ W,
                                                   const float* __restrict__ bias) {
    __shared__ float W_sh[128 * Pn];   // 35840 B
    __shared__ float e_sh[8 * 128];    // 4096 B

    const int tid   = threadIdx.x;
    const int group = blockIdx.x >> 2;
    const int chunk = blockIdx.x & 3;
    const int b0    = group * 8;
    const int e0    = chunk * 128;

    // W chunk rows e0..e0+127 are contiguous floats (full rows), 16B-aligned offset
    {
        const float4* Wv = (const float4*)(W + (size_t)e0 * Pn);
        float4* Ws = (float4*)W_sh;
        #pragma unroll 4
        for (int i = tid; i < 128 * Pn / 4; i += 576) Ws[i] = Wv[i];
        if (tid < 256) {   // 8 rows x 32 float4
            int r = tid >> 5, j = tid & 31;
            ((float4*)(e_sh + r * 128))[j] =
                ((const float4*)(emb + (size_t)(b0 + r) * En + e0))[j];
        }
    }
    __syncthreads();

    if (tid < 560) {
        const int r = tid / 70, c = tid - r * 70;
        const float* er = e_sh + r * 128;
        float a0 = 0.f, a1 = 0.f, a2 = 0.f, a3 = 0.f;
        #pragma unroll 8
        for (int e = 0; e < 128; e += 4) {
            float4 ev = *(const float4*)(er + e);
            a0 = fmaf(ev.x, W_sh[(e + 0) * Pn + c], a0);
            a1 = fmaf(ev.y, W_sh[(e + 1) * Pn + c], a1);
            a2 = fmaf(ev.z, W_sh[(e + 2) * Pn + c], a2);
            a3 = fmaf(ev.w, W_sh[(e + 3) * Pn + c], a3);
        }
        float acc = (a0 + a1) + (a2 + a3);
        if (chunk == 0) acc += bias[c];
        g_pp[((size_t)(b0 + r) * 4 + chunk) * 72 + c] = acc;
    }
}

__device__ __forceinline__ float pp_sum(int b, int i) {
    const float* p = g_pp + (size_t)b * 4 * 72 + i;
    return (p[0] + p[72]) + (p[144] + p[216]);
}

// ===================== K2: z = beta * cos-sim — pure stream =====================
#define K2_TB 16384
#define K2_SMEM_BYTES (4 * K2_TB + 80 * 4 + 12 * 8)

__global__ __launch_bounds__(256) void sim_kernel(const float* __restrict__ memory) {
    extern __shared__ float smem[];
    float*    tiles = smem;                       // 16384 floats (4 x 16KB)
    float*    k_sh  = smem + 16384;               // 64
    float*    red   = k_sh + 64;                  // 2
    float*    ps    = red + 2;                    // 1 (proj[64] sum)
    uint64_t* mbars = (uint64_t*)(k_sh + 80);     // full[0..7], empty[8..11]

    const int b    = blockIdx.x >> 1;
    const int half = blockIdx.x & 1;
    const int tid  = threadIdx.x;
    const int lane = tid & 31;
    const int wid  = tid >> 5;
    const float* mb = memory + ((size_t)b * Nn + half * 512) * Mn;

    const uint32_t tiles_u = s2u(tiles);
    const uint32_t mbar0   = s2u(mbars);

    if (tid == 0) {
        #pragma unroll
        for (int t = 0; t < 8; ++t) mbar_init(mbar0 + 8u * t, 1);
        #pragma unroll
        for (int k = 0; k < 4; ++k) mbar_init(mbar0 + 8u * (8 + k), 32);
    }
    // preamble: k = chunk-sum, ksq reduce; thread 64 sums proj[64] for beta
    if (tid < 64) {
        float v = pp_sum(b, tid);
        k_sh[tid] = v;
        float ksq = v * v;
        #pragma unroll
        for (int o = 16; o; o >>= 1) ksq += __shfl_xor_sync(0xffffffffu, ksq, o);
        if (lane == 0) red[wid] = ksq;
    } else if (tid == 64) {
        ps[0] = pp_sum(b, 64);
    }
    __syncthreads();
    const float beta  = softplusf(ps[0]);
    const float knorm = sqrtf(red[0] + red[1]);

    // producer: thread 255 (warp 7 -> its own tile last; no self-deadlock)
    if (tid == 255) {
        #pragma unroll
        for (int i = 0; i < 8; ++i) {
            int buf = i & 3;
            if (i >= 4) mbar_wait(mbar0 + 8u * (8 + buf), 0);
            uint32_t fb = mbar0 + 8u * i;
            mbar_expect_tx(fb, K2_TB);
            bulk_g2s(tiles_u + buf * K2_TB, mb + (size_t)i * 64 * Mn, K2_TB, fb);
        }
    }

    // consumer: warp wid -> tile wid; thread -> rows 2*lane, 2*lane+1
    mbar_wait(mbar0 + 8u * wid, 0);
    const float4* base = (const float4*)(tiles + (wid & 3) * 4096);
    const float4* va = base + lane * 32;
    const float4* vb = va + 16;
    const float4* k4 = (const float4*)k_sh;
    const int rot = lane & 15;
    float d0 = 0.f, q0 = 0.f, d1 = 0.f, q1 = 0.f;
    #pragma unroll 2
    for (int j = 0; j < 16; ++j) {
        int j0 = (j + rot) & 15;
        float4 kk = k4[j0];
        float4 v0 = va[j0];
        float4 v1 = vb[j0];
        d0 = fmaf(kk.x, v0.x, fmaf(kk.y, v0.y, fmaf(kk.z, v0.z, fmaf(kk.w, v0.w, d0))));
        q0 = fmaf(v0.x, v0.x, fmaf(v0.y, v0.y, fmaf(v0.z, v0.z, fmaf(v0.w, v0.w, q0))));
        d1 = fmaf(kk.x, v1.x, fmaf(kk.y, v1.y, fmaf(kk.z, v1.z, fmaf(kk.w, v1.w, d1))));
        q1 = fmaf(v1.x, v1.x, fmaf(v1.y, v1.y, fmaf(v1.z, v1.z, fmaf(v1.w, v1.w, q1))));
    }
    float z0 = beta * d0 / (knorm * sqrtf(q0) + EPSf);
    float z1 = beta * d1 / (knorm * sqrtf(q1) + EPSf);
    mbar_arrive(mbar0 + 8u * (8 + (wid & 3)));
    ((float2*)(g_z + (size_t)b * Nn + half * 512 + wid * 64))[lane] = make_float2(z0, z1);
}

// ===================== K34: softmax chain + weighted read (reverse b for L2 reuse) ===
__device__ __forceinline__ float block_sum512(float v, float* red, int lane, int wid) {
    #pragma unroll
    for (int o = 16; o; o >>= 1) v += __shfl_xor_sync(0xffffffffu, v, o);
    if (lane == 0) red[wid] = v;
    __syncthreads();
    if (wid == 0) {
        float x = (lane < 16) ? red[lane] : 0.0f;
        #pragma unroll
        for (int o = 8; o; o >>= 1) x += __shfl_xor_sync(0xffffffffu, x, o);
        if (lane == 0) red[16] = x;
    }
    __syncthreads();
    return red[16];
}

__global__ __launch_bounds__(512) void read_kernel(const float* __restrict__ w_prev,
                                                   const float* __restrict__ memory,
                                                   float* __restrict__ out_md,
                                                   float* __restrict__ out_w) {
    __shared__ float wg_sh[Nn];     // reused as partials [16][64] at the end
    __shared__ float w_sh[Nn];
    __shared__ float red[17];
    __shared__ float sc[5];         // g, s0, s1, s2, y
    const int b    = (Bn - 1) - blockIdx.x;   // REVERSED: hit sim's L2 residue first
    const int tid  = threadIdx.x;
    const int lane = tid & 31;
    const int wid  = tid >> 5;
    const float* mb = memory + (size_t)b * Nn * Mn;

    if (tid == 0) {
        float p65 = pp_sum(b, 65);
        float a0  = pp_sum(b, 66), a1 = pp_sum(b, 67), a2 = pp_sum(b, 68);
        float p69 = pp_sum(b, 69);
        float mx = fmaxf(a0, fmaxf(a1, a2));
        float e0 = expf(a0 - mx), e1 = expf(a1 - mx), e2 = expf(a2 - mx);
        float dn = e0 + e1 + e2;
        sc[0] = 1.0f / (1.0f + expf(-p65));
        sc[1] = e0 / dn; sc[2] = e1 / dn; sc[3] = e2 / dn;
        sc[4] = 1.0f + softplusf(p69);
    }

    float2 z2 = ((const float2*)(g_z + (size_t)b * Nn))[tid];
    float2 wprev2 = ((const float2*)(w_prev + (size_t)b * Nn))[tid];

    float e0 = expf(z2.x), e1 = expf(z2.y);     // |z| <= beta, no max pass needed
    float denom = block_sum512(e0 + e1, red, lane, wid);   // sc visible after its syncs
    float inv_d = 1.0f / denom;
    const float gg = sc[0], s0 = sc[1], s1 = sc[2], s2 = sc[3], yy = sc[4];
    float omg = 1.0f - gg;
    float wg0 = fmaf(gg, e0 * inv_d, omg * wprev2.x);
    float wg1 = fmaf(gg, e1 * inv_d, omg * wprev2.y);
    wg_sh[2 * tid]     = wg0;
    wg_sh[2 * tid + 1] = wg1;
    __syncthreads();
    float wt0 = s0 * wg1 + s1 * wg0 + s2 * wg_sh[(2 * tid - 1) & (Nn - 1)];
    float wt1 = s0 * wg_sh[(2 * tid + 2) & (Nn - 1)] + s1 * wg1 + s2 * wg0;
    float wp0 = __powf(wt0, yy);
    float wp1 = __powf(wt1, yy);
    float psum = block_sum512(wp0 + wp1, red, lane, wid);
    float inv_p = 1.0f / (psum + EPSf);
    float wv0 = wp0 * inv_p, wv1 = wp1 * inv_p;
    w_sh[2 * tid]     = wv0;
    w_sh[2 * tid + 1] = wv1;
    ((float2*)(out_w + (size_t)b * Nn))[tid] = make_float2(wv0, wv1);
    __syncthreads();   // w_sh ready; wg_sh reads done -> reuse as partials

    const int sub  = lane & 15;
    const int half = lane >> 4;
    float4 acc = make_float4(0.f, 0.f, 0.f, 0.f);
    #pragma unroll 4
    for (int it = 0; it < 32; ++it) {
        int n = it * 32 + wid * 2 + half;
        float4 v = ((const float4*)(mb + (size_t)n * Mn))[sub];
        float wn = w_sh[n];
        acc.x = fmaf(wn, v.x, acc.x);
        acc.y = fmaf(wn, v.y, acc.y);
        acc.z = fmaf(wn, v.z, acc.z);
        acc.w = fmaf(wn, v.w, acc.w);
    }
    acc.x += __shfl_xor_sync(0xffffffffu, acc.x, 16);
    acc.y += __shfl_xor_sync(0xffffffffu, acc.y, 16);
    acc.z += __shfl_xor_sync(0xffffffffu, acc.z, 16);
    acc.w += __shfl_xor_sync(0xffffffffu, acc.w, 16);
    if (half == 0)
        ((float4*)wg_sh)[wid * 16 + sub] = acc;     // partials [16][64]
    __syncthreads();
    if (tid < Mn) {
        float s = 0.0f;
        #pragma unroll
        for (int w = 0; w < 16; ++w) s += wg_sh[w * 64 + tid];
        out_md[(size_t)b * Mn + tid] = s;
    }
}

extern "C" void kernel_launch(void* const* d_in, const int* in_sizes, int n_in,
                              void* d_out, int out_size) {
    const float* embeddings = (const float*)d_in[0];   // [1024, 512]
    const float* w_prev     = (const float*)d_in[1];   // [1024, 1024]
    const float* memory     = (const float*)d_in[2];   // [1024, 1024, 64]
    const float* W          = (const float*)d_in[3];   // [512, 70]
    const float* bias       = (const float*)d_in[4];   // [70]

    float* out_md = (float*)d_out;             // memory_data [1024, 64] first
    float* out_w  = out_md + (size_t)Bn * Mn;  // then w [1024, 1024]

    proj_kernel<<<512, 576>>>(embeddings, W, bias);
    cudaFuncSetAttribute(sim_kernel, cudaFuncAttributeMaxDynamicSharedMemorySize, K2_SMEM_BYTES);
    sim_kernel<<<2 * Bn, 256, K2_SMEM_BYTES>>>(memory);
    read_kernel<<<Bn, 512>>>(w_prev, memory, out_md, out_w);
}